// round 3
// baseline (speedup 1.0000x reference)
#include <cuda_runtime.h>
#include <math.h>

#define NN 50000
#define NE 800000
#define NH 4
#define NEG 0.2f

// ---------------- scratch (static device globals; no allocs allowed) ----------
__device__ float g_proj1[NN * 400];   // layer1 projection [N, H*100]
__device__ float g_x1[NN * 400];      // layer1 output / layer2 input
__device__ float g_proj2[NN * 512];   // layer2 projection [N, H*128]
__device__ float g_el[NN * NH];
__device__ float g_er[NN * NH];
__device__ float g_m[NN * NH];
__device__ float g_s[NN * NH];
__device__ float g_ex[NE * NH];       // per-edge e, then exp(e - m)

// ---------------- helpers ----------------------------------------------------
__device__ __forceinline__ float lrelu(float v) { return v > 0.f ? v : NEG * v; }

__device__ __forceinline__ void atomicMaxFloat(float* addr, float v) {
    int* ia = (int*)addr;
    int old = *ia;
    while (true) {
        float f = __int_as_float(old);
        if (f >= v) break;                       // NaN init -> false -> replace
        int assumed = old;
        old = atomicCAS(ia, assumed, __float_as_int(v));
        if (old == assumed) break;
    }
}

// ---------------- init kernels -----------------------------------------------
__global__ void k_zero(float* p, int n) {
    int i = blockIdx.x * blockDim.x + threadIdx.x;
    if (i < n) p[i] = 0.f;
}
__global__ void k_init_ms(float* m, float* s, int n) {
    int i = blockIdx.x * blockDim.x + threadIdx.x;
    if (i < n) { m[i] = -INFINITY; s[i] = 0.f; }
}

// ---------------- SGEMM: C[MxN] = A[MxK] * B[KxN] (row-major, fp32) ----------
template <int BM, int BN, int BK, int TM, int TN>
__global__ void k_sgemm(const float* __restrict__ A, const float* __restrict__ B,
                        float* __restrict__ C, int M, int N, int K) {
    __shared__ float As[BK][BM];
    __shared__ float Bs[BK][BN];
    const int tid = threadIdx.x;                 // 256 threads
    const int tx = tid % (BN / TN);              // 16
    const int ty = tid / (BN / TN);              // 16
    const int brow = blockIdx.y, bcol = blockIdx.x;

    float acc[TM][TN];
#pragma unroll
    for (int i = 0; i < TM; i++)
#pragma unroll
        for (int j = 0; j < TN; j++) acc[i][j] = 0.f;

    for (int k0 = 0; k0 < K; k0 += BK) {
        // A tile -> transposed into As[k][m]
        for (int i = tid; i < BM * BK; i += 256) {
            int m = i / BK, k = i % BK;
            int gm = brow * BM + m, gk = k0 + k;
            As[k][m] = (gm < M && gk < K) ? A[(size_t)gm * K + gk] : 0.f;
        }
        // B tile
        for (int i = tid; i < BK * BN; i += 256) {
            int k = i / BN, n = i % BN;
            int gk = k0 + k, gn = bcol * BN + n;
            Bs[k][n] = (gk < K && gn < N) ? B[(size_t)gk * N + gn] : 0.f;
        }
        __syncthreads();
#pragma unroll
        for (int k = 0; k < BK; k++) {
            float a[TM], b[TN];
#pragma unroll
            for (int i = 0; i < TM; i++) a[i] = As[k][ty * TM + i];
#pragma unroll
            for (int j = 0; j < TN; j++) b[j] = Bs[k][tx * TN + j];
#pragma unroll
            for (int i = 0; i < TM; i++)
#pragma unroll
                for (int j = 0; j < TN; j++) acc[i][j] += a[i] * b[j];
        }
        __syncthreads();
    }
#pragma unroll
    for (int i = 0; i < TM; i++) {
        int gm = brow * BM + ty * TM + i;
        if (gm >= M) continue;
#pragma unroll
        for (int j = 0; j < TN; j++) {
            int gn = bcol * BN + tx * TN + j;
            if (gn < N) C[(size_t)gm * N + gn] = acc[i][j];
        }
    }
}

// ---------------- per-node attention scores el/er ----------------------------
// block = 128 threads = 4 warps, one warp per head; grid = N nodes
__global__ void k_scores(const float* __restrict__ proj,
                         const float* __restrict__ al, const float* __restrict__ ar,
                         float* __restrict__ el, float* __restrict__ er, int Dh) {
    int n = blockIdx.x;
    int w = threadIdx.x >> 5, lane = threadIdx.x & 31;
    const float* p = proj + (size_t)n * NH * Dh + w * Dh;
    float sl = 0.f, sr = 0.f;
    for (int d = lane; d < Dh; d += 32) {
        float v = p[d];
        sl += v * al[w * Dh + d];
        sr += v * ar[w * Dh + d];
    }
#pragma unroll
    for (int o = 16; o > 0; o >>= 1) {
        sl += __shfl_down_sync(0xffffffffu, sl, o);
        sr += __shfl_down_sync(0xffffffffu, sr, o);
    }
    if (lane == 0) { el[n * NH + w] = sl; er[n * NH + w] = sr; }
}

// ---------------- edge pass 1: e = lrelu(el[src]+er[dst]); segment max -------
__global__ void k_edge_max(const float* __restrict__ el, const float* __restrict__ er,
                           const int* __restrict__ src, const int* __restrict__ dst,
                           float* __restrict__ m, float* __restrict__ ex) {
    int i = blockIdx.x * blockDim.x + threadIdx.x;
    if (i >= NE * NH) return;
    int e = i >> 2, h = i & 3;
    int s = src[e], d = dst[e];
    float v = lrelu(el[s * NH + h] + er[d * NH + h]);
    ex[i] = v;
    atomicMaxFloat(&m[d * NH + h], v);
}

__global__ void k_fix_m(float* m, int n) {
    int i = blockIdx.x * blockDim.x + threadIdx.x;
    if (i < n && !isfinite(m[i])) m[i] = 0.f;
}

// ---------------- edge pass 2: ex = exp(e - m[dst]); segment sum -------------
__global__ void k_edge_exp(const int* __restrict__ dst, const float* __restrict__ m,
                           float* __restrict__ ex, float* __restrict__ s) {
    int i = blockIdx.x * blockDim.x + threadIdx.x;
    if (i >= NE * NH) return;
    int e = i >> 2, h = i & 3;
    int d = dst[e];
    float v = expf(ex[i] - m[d * NH + h]);
    ex[i] = v;
    atomicAdd(&s[d * NH + h], v);
}

// ---------------- edge pass 3: out[dst] += proj[src] * alpha -----------------
// one block (128 thr) per edge; F = H*Dh, F%4==0 and Dh%4==0
__global__ void k_aggregate(const float* __restrict__ proj, const float* __restrict__ ex,
                            const float* __restrict__ ssum,
                            const int* __restrict__ src, const int* __restrict__ dst,
                            float* __restrict__ out, int Dh) {
    int e = blockIdx.x;
    __shared__ float alpha[NH];
    __shared__ int sh_s, sh_d;
    if (threadIdx.x == 0) { sh_s = src[e]; sh_d = dst[e]; }
    __syncthreads();
    int d = sh_d, sn = sh_s;
    if (threadIdx.x < NH)
        alpha[threadIdx.x] = ex[e * NH + threadIdx.x] / (ssum[d * NH + threadIdx.x] + 1e-9f);
    __syncthreads();
    int F4 = NH * Dh / 4;
    const float4* p = (const float4*)(proj + (size_t)sn * NH * Dh);
    float* o = out + (size_t)d * NH * Dh;
    for (int f4 = threadIdx.x; f4 < F4; f4 += blockDim.x) {
        float a = alpha[(f4 * 4) / Dh];
        float4 v = p[f4];
        int f = f4 * 4;
        atomicAdd(&o[f + 0], v.x * a);
        atomicAdd(&o[f + 1], v.y * a);
        atomicAdd(&o[f + 2], v.z * a);
        atomicAdd(&o[f + 3], v.w * a);
    }
}

// ---------------- finalize: bias (+ optional leaky relu) ---------------------
__global__ void k_finalize(float* __restrict__ x, const float* __restrict__ b,
                           int n, int F, int act) {
    int i = blockIdx.x * blockDim.x + threadIdx.x;
    if (i >= n) return;
    float v = x[i] + b[i % F];
    x[i] = act ? lrelu(v) : v;
}

// ---------------- launch -----------------------------------------------------
extern "C" void kernel_launch(void* const* d_in, const int* in_sizes, int n_in,
                              void* d_out, int out_size) {
    const float* init_emb = (const float*)d_in[0];
    const float* W1  = (const float*)d_in[1];
    const float* al1 = (const float*)d_in[2];
    const float* ar1 = (const float*)d_in[3];
    const float* b1  = (const float*)d_in[4];
    const float* W2  = (const float*)d_in[5];
    const float* al2 = (const float*)d_in[6];
    const float* ar2 = (const float*)d_in[7];
    const float* b2  = (const float*)d_in[8];
    const int*   src = (const int*)d_in[9];
    const int*   dst = (const int*)d_in[10];
    float* out = (float*)d_out;

    float *proj1, *x1, *proj2, *el, *er, *m, *s, *ex;
    cudaGetSymbolAddress((void**)&proj1, g_proj1);
    cudaGetSymbolAddress((void**)&x1,    g_x1);
    cudaGetSymbolAddress((void**)&proj2, g_proj2);
    cudaGetSymbolAddress((void**)&el,    g_el);
    cudaGetSymbolAddress((void**)&er,    g_er);
    cudaGetSymbolAddress((void**)&m,     g_m);
    cudaGetSymbolAddress((void**)&s,     g_s);
    cudaGetSymbolAddress((void**)&ex,    g_ex);

    const int EH = NE * NH;        // 3.2M
    const int NHtot = NN * NH;     // 200k
    dim3 t256(256);

    // ===================== layer 1 (Fin=300, Fout=400, Dh=100) ===============
    {
        dim3 grid((400 + 63) / 64, (NN + 63) / 64);
        k_sgemm<64, 64, 16, 4, 4><<<grid, 256>>>(init_emb, W1, proj1, NN, 400, 300);
    }
    k_scores<<<NN, 128>>>(proj1, al1, ar1, el, er, 100);
    k_init_ms<<<(NHtot + 255) / 256, t256>>>(m, s, NHtot);
    k_edge_max<<<(EH + 255) / 256, t256>>>(el, er, src, dst, m, ex);
    k_fix_m<<<(NHtot + 255) / 256, t256>>>(m, NHtot);
    k_edge_exp<<<(EH + 255) / 256, t256>>>(dst, m, ex, s);
    k_zero<<<(NN * 400 + 255) / 256, t256>>>(x1, NN * 400);
    k_aggregate<<<NE, 128>>>(proj1, ex, s, src, dst, x1, 100);
    k_finalize<<<(NN * 400 + 255) / 256, t256>>>(x1, b1, NN * 400, 400, 1);

    // ===================== layer 2 (Fin=400, Fout=512, Dh=128) ===============
    {
        dim3 grid((512 + 63) / 64, (NN + 63) / 64);
        k_sgemm<64, 64, 16, 4, 4><<<grid, 256>>>(x1, W2, proj2, NN, 512, 400);
    }
    k_scores<<<NN, 128>>>(proj2, al2, ar2, el, er, 128);
    k_init_ms<<<(NHtot + 255) / 256, t256>>>(m, s, NHtot);
    k_edge_max<<<(EH + 255) / 256, t256>>>(el, er, src, dst, m, ex);
    k_fix_m<<<(NHtot + 255) / 256, t256>>>(m, NHtot);
    k_edge_exp<<<(EH + 255) / 256, t256>>>(dst, m, ex, s);
    k_zero<<<(NN * 512 + 255) / 256, t256>>>(out, NN * 512);
    k_aggregate<<<NE, 128>>>(proj2, ex, s, src, dst, out, 128);
    k_finalize<<<(NN * 512 + 255) / 256, t256>>>(out, b2, NN * 512, 512, 0);
}

// round 6
// speedup vs baseline: 2.0155x; 2.0155x over previous
#include <cuda_runtime.h>
#include <math.h>

#define NN 50000
#define NE 800000
#define NH 4
#define NEG 0.2f

// ---------------- scratch (static device globals; no allocs allowed) ----------
__device__ float g_proj1[NN * 400];
__device__ float g_x1[NN * 400];
__device__ float g_proj2[NN * 512];
__device__ float g_el[NN * NH];
__device__ float g_er[NN * NH];
__device__ float g_m[NN * NH];
__device__ float g_s[NN * NH];
__device__ float g_ex[NE * NH];

// ---------------- helpers ----------------------------------------------------
__device__ __forceinline__ float lrelu(float v) { return v > 0.f ? v : NEG * v; }

__device__ __forceinline__ unsigned f2tf32(float f) {
    unsigned r;
    asm("cvt.rna.tf32.f32 %0, %1;" : "=r"(r) : "f"(f));
    return r;
}

__device__ __forceinline__ void mma_tf32(float c[4], const unsigned a[4], const unsigned b[2]) {
    asm volatile(
        "mma.sync.aligned.m16n8k8.row.col.f32.tf32.tf32.f32 "
        "{%0,%1,%2,%3}, {%4,%5,%6,%7}, {%8,%9}, {%0,%1,%2,%3};"
        : "+f"(c[0]), "+f"(c[1]), "+f"(c[2]), "+f"(c[3])
        : "r"(a[0]), "r"(a[1]), "r"(a[2]), "r"(a[3]), "r"(b[0]), "r"(b[1]));
}

__device__ __forceinline__ void red4(float* p, float x, float y, float z, float w) {
    asm volatile("red.global.add.v4.f32 [%0], {%1,%2,%3,%4};"
                 :: "l"(p), "f"(x), "f"(y), "f"(z), "f"(w) : "memory");
}

__device__ __forceinline__ void atomicMaxFloat(float* addr, float v) {
    int* ia = (int*)addr;
    int old = *ia;
    while (true) {
        float f = __int_as_float(old);
        if (f >= v) break;
        int assumed = old;
        old = atomicCAS(ia, assumed, __float_as_int(v));
        if (old == assumed) break;
    }
}

// ---------------- init kernels -----------------------------------------------
__global__ void k_zero(float* p, int n) {
    int i = blockIdx.x * blockDim.x + threadIdx.x;
    if (i < n) p[i] = 0.f;
}
__global__ void k_init_ms(float* m, float* s, int n) {
    int i = blockIdx.x * blockDim.x + threadIdx.x;
    if (i < n) { m[i] = -INFINITY; s[i] = 0.f; }
}

// ---------------- TF32 tensor-core GEMM: C[MxN] = A[MxK]*B[KxN] row-major ----
#define BM 128
#define BN 128
#define BK 16
#define A_STRIDE (BK + 4)    // 20: conflict-free for frag reads, 16B-aligned stores
#define B_STRIDE (BN + 8)    // 136: conflict-free for frag reads, 16B-aligned stores

__global__ void __launch_bounds__(256, 2)
k_gemm_tf32(const float* __restrict__ A, const float* __restrict__ B,
            float* __restrict__ C, int M, int N, int K) {
    __shared__ unsigned As[BM][A_STRIDE];
    __shared__ unsigned Bs[BK][B_STRIDE];

    const int tid  = threadIdx.x;
    const int lane = tid & 31;
    const int warp = tid >> 5;
    const int g    = lane >> 2;          // group id 0..7
    const int t4   = lane & 3;           // thread-in-group 0..3
    const int wm   = warp & 1;           // 2 warps along M (64 rows each)
    const int wn   = warp >> 1;          // 4 warps along N (32 cols each)
    const int bm0  = blockIdx.y * BM;
    const int bn0  = blockIdx.x * BN;

    float c[4][4][4];
#pragma unroll
    for (int mi = 0; mi < 4; mi++)
#pragma unroll
        for (int ni = 0; ni < 4; ni++)
#pragma unroll
            for (int q = 0; q < 4; q++) c[mi][ni][q] = 0.f;

    const int nk = (K + BK - 1) / BK;
    for (int kt = 0; kt < nk; kt++) {
        const int k0 = kt * BK;
        // ---- load A tile: 128x16 = 512 float4, 2 per thread ----
#pragma unroll
        for (int u = 0; u < 2; u++) {
            int idx = tid + u * 256;
            int row = idx >> 2;
            int col = (idx & 3) * 4;
            int gm = bm0 + row, gk = k0 + col;
            float4 v = make_float4(0.f, 0.f, 0.f, 0.f);
            if (gm < M) {
                if (gk + 3 < K) v = *(const float4*)(A + (size_t)gm * K + gk);
                else {
                    const float* ap = A + (size_t)gm * K;
                    if (gk + 0 < K) v.x = ap[gk + 0];
                    if (gk + 1 < K) v.y = ap[gk + 1];
                    if (gk + 2 < K) v.z = ap[gk + 2];
                }
            }
            As[row][col + 0] = f2tf32(v.x);
            As[row][col + 1] = f2tf32(v.y);
            As[row][col + 2] = f2tf32(v.z);
            As[row][col + 3] = f2tf32(v.w);
        }
        // ---- load B tile: 16x128 = 512 float4, 2 per thread ----
#pragma unroll
        for (int u = 0; u < 2; u++) {
            int idx = tid + u * 256;
            int row = idx >> 5;
            int col = (idx & 31) * 4;
            int gk = k0 + row, gn = bn0 + col;
            float4 v = make_float4(0.f, 0.f, 0.f, 0.f);
            if (gk < K) {
                if (gn + 3 < N) v = *(const float4*)(B + (size_t)gk * N + gn);
                else {
                    const float* bp = B + (size_t)gk * N;
                    if (gn + 0 < N) v.x = bp[gn + 0];
                    if (gn + 1 < N) v.y = bp[gn + 1];
                    if (gn + 2 < N) v.z = bp[gn + 2];
                }
            }
            Bs[row][col + 0] = f2tf32(v.x);
            Bs[row][col + 1] = f2tf32(v.y);
            Bs[row][col + 2] = f2tf32(v.z);
            Bs[row][col + 3] = f2tf32(v.w);
        }
        __syncthreads();

#pragma unroll
        for (int kk = 0; kk < BK; kk += 8) {
            unsigned af[4][4], bf[4][2];
#pragma unroll
            for (int mi = 0; mi < 4; mi++) {
                int r0 = wm * 64 + mi * 16;
                af[mi][0] = As[r0 + g    ][kk + t4    ];
                af[mi][1] = As[r0 + g + 8][kk + t4    ];
                af[mi][2] = As[r0 + g    ][kk + t4 + 4];
                af[mi][3] = As[r0 + g + 8][kk + t4 + 4];
            }
#pragma unroll
            for (int ni = 0; ni < 4; ni++) {
                int c0 = wn * 32 + ni * 8;
                bf[ni][0] = Bs[kk + t4    ][c0 + g];
                bf[ni][1] = Bs[kk + t4 + 4][c0 + g];
            }
#pragma unroll
            for (int mi = 0; mi < 4; mi++)
#pragma unroll
                for (int ni = 0; ni < 4; ni++)
                    mma_tf32(c[mi][ni], af[mi], bf[ni]);
        }
        __syncthreads();
    }

    // ---- epilogue ----
#pragma unroll
    for (int mi = 0; mi < 4; mi++) {
        int row0 = bm0 + wm * 64 + mi * 16;
#pragma unroll
        for (int ni = 0; ni < 4; ni++) {
            int col0 = bn0 + wn * 32 + ni * 8 + 2 * t4;
            int r = row0 + g;
            if (r < M) {
                if (col0     < N) C[(size_t)r * N + col0    ] = c[mi][ni][0];
                if (col0 + 1 < N) C[(size_t)r * N + col0 + 1] = c[mi][ni][1];
            }
            r = row0 + g + 8;
            if (r < M) {
                if (col0     < N) C[(size_t)r * N + col0    ] = c[mi][ni][2];
                if (col0 + 1 < N) C[(size_t)r * N + col0 + 1] = c[mi][ni][3];
            }
        }
    }
}

// ---------------- per-node attention scores el/er ----------------------------
__global__ void k_scores(const float* __restrict__ proj,
                         const float* __restrict__ al, const float* __restrict__ ar,
                         float* __restrict__ el, float* __restrict__ er, int Dh) {
    int n = blockIdx.x;
    int w = threadIdx.x >> 5, lane = threadIdx.x & 31;
    const float* p = proj + (size_t)n * NH * Dh + w * Dh;
    float sl = 0.f, sr = 0.f;
    for (int d = lane; d < Dh; d += 32) {
        float v = p[d];
        sl += v * al[w * Dh + d];
        sr += v * ar[w * Dh + d];
    }
#pragma unroll
    for (int o = 16; o > 0; o >>= 1) {
        sl += __shfl_down_sync(0xffffffffu, sl, o);
        sr += __shfl_down_sync(0xffffffffu, sr, o);
    }
    if (lane == 0) { el[n * NH + w] = sl; er[n * NH + w] = sr; }
}

// ---------------- edge pass 1: e = lrelu(el[src]+er[dst]); segment max -------
__global__ void k_edge_max(const float* __restrict__ el, const float* __restrict__ er,
                           const int* __restrict__ src, const int* __restrict__ dst,
                           float* __restrict__ m, float* __restrict__ ex) {
    int i = blockIdx.x * blockDim.x + threadIdx.x;
    if (i >= NE * NH) return;
    int e = i >> 2, h = i & 3;
    int s = src[e], d = dst[e];
    float v = lrelu(el[s * NH + h] + er[d * NH + h]);
    ex[i] = v;
    atomicMaxFloat(&m[d * NH + h], v);
}

__global__ void k_fix_m(float* m, int n) {
    int i = blockIdx.x * blockDim.x + threadIdx.x;
    if (i < n && !isfinite(m[i])) m[i] = 0.f;
}

// ---------------- edge pass 2: ex = exp(e - m[dst]); segment sum -------------
__global__ void k_edge_exp(const int* __restrict__ dst, const float* __restrict__ m,
                           float* __restrict__ ex, float* __restrict__ s) {
    int i = blockIdx.x * blockDim.x + threadIdx.x;
    if (i >= NE * NH) return;
    int e = i >> 2, h = i & 3;
    int d = dst[e];
    float v = expf(ex[i] - m[d * NH + h]);
    ex[i] = v;
    atomicAdd(&s[d * NH + h], v);
}

// ---------------- edge pass 3: out[dst] += proj[src]*alpha (warp/edge, v4 red)
__global__ void k_aggregate(const float* __restrict__ proj, const float* __restrict__ ex,
                            const float* __restrict__ ssum,
                            const int* __restrict__ src, const int* __restrict__ dst,
                            float* __restrict__ out, int Dh) {
    int gw = (blockIdx.x * blockDim.x + threadIdx.x) >> 5;
    if (gw >= NE) return;
    int lane = threadIdx.x & 31;
    int sn = src[gw];
    int d  = dst[gw];
    float a = 0.f;
    if (lane < NH) a = ex[gw * NH + lane] / (ssum[d * NH + lane] + 1e-9f);
    float a0 = __shfl_sync(0xffffffffu, a, 0);
    float a1 = __shfl_sync(0xffffffffu, a, 1);
    float a2 = __shfl_sync(0xffffffffu, a, 2);
    float a3 = __shfl_sync(0xffffffffu, a, 3);
    int F4 = NH * Dh / 4;
    const float4* p = (const float4*)(proj + (size_t)sn * NH * Dh);
    float* o = out + (size_t)d * NH * Dh;
    for (int f4 = lane; f4 < F4; f4 += 32) {
        int h = (f4 * 4) / Dh;
        float al = h == 0 ? a0 : h == 1 ? a1 : h == 2 ? a2 : a3;
        float4 v = p[f4];
        red4(&o[f4 * 4], v.x * al, v.y * al, v.z * al, v.w * al);
    }
}

// ---------------- finalize: bias (+ optional leaky relu) ---------------------
__global__ void k_finalize(float* __restrict__ x, const float* __restrict__ b,
                           int n, int F, int act) {
    int i = blockIdx.x * blockDim.x + threadIdx.x;
    if (i >= n) return;
    float v = x[i] + b[i % F];
    x[i] = act ? lrelu(v) : v;
}

// ---------------- launch -----------------------------------------------------
extern "C" void kernel_launch(void* const* d_in, const int* in_sizes, int n_in,
                              void* d_out, int out_size) {
    const float* init_emb = (const float*)d_in[0];
    const float* W1  = (const float*)d_in[1];
    const float* al1 = (const float*)d_in[2];
    const float* ar1 = (const float*)d_in[3];
    const float* b1  = (const float*)d_in[4];
    const float* W2  = (const float*)d_in[5];
    const float* al2 = (const float*)d_in[6];
    const float* ar2 = (const float*)d_in[7];
    const float* b2  = (const float*)d_in[8];
    const int*   src = (const int*)d_in[9];
    const int*   dst = (const int*)d_in[10];
    float* out = (float*)d_out;

    float *proj1, *x1, *proj2, *el, *er, *m, *s, *ex;
    cudaGetSymbolAddress((void**)&proj1, g_proj1);
    cudaGetSymbolAddress((void**)&x1,    g_x1);
    cudaGetSymbolAddress((void**)&proj2, g_proj2);
    cudaGetSymbolAddress((void**)&el,    g_el);
    cudaGetSymbolAddress((void**)&er,    g_er);
    cudaGetSymbolAddress((void**)&m,     g_m);
    cudaGetSymbolAddress((void**)&s,     g_s);
    cudaGetSymbolAddress((void**)&ex,    g_ex);

    const int EH = NE * NH;
    const int NHtot = NN * NH;
    dim3 t256(256);
    const int aggBlocks = (NE * 32 + 255) / 256;   // one warp per edge

    // ===================== layer 1 (Fin=300, Fout=400, Dh=100) ===============
    {
        dim3 grid((400 + BN - 1) / BN, (NN + BM - 1) / BM);
        k_gemm_tf32<<<grid, 256>>>(init_emb, W1, proj1, NN, 400, 300);
    }
    k_scores<<<NN, 128>>>(proj1, al1, ar1, el, er, 100);
    k_init_ms<<<(NHtot + 255) / 256, t256>>>(m, s, NHtot);
    k_edge_max<<<(EH + 255) / 256, t256>>>(el, er, src, dst, m, ex);
    k_fix_m<<<(NHtot + 255) / 256, t256>>>(m, NHtot);
    k_edge_exp<<<(EH + 255) / 256, t256>>>(dst, m, ex, s);
    k_zero<<<(NN * 400 + 255) / 256, t256>>>(x1, NN * 400);
    k_aggregate<<<aggBlocks, 256>>>(proj1, ex, s, src, dst, x1, 100);
    k_finalize<<<(NN * 400 + 255) / 256, t256>>>(x1, b1, NN * 400, 400, 1);

    // ===================== layer 2 (Fin=400, Fout=512, Dh=128) ===============
    {
        dim3 grid((512 + BN - 1) / BN, (NN + BM - 1) / BM);
        k_gemm_tf32<<<grid, 256>>>(x1, W2, proj2, NN, 512, 400);
    }
    k_scores<<<NN, 128>>>(proj2, al2, ar2, el, er, 128);
    k_init_ms<<<(NHtot + 255) / 256, t256>>>(m, s, NHtot);
    k_edge_max<<<(EH + 255) / 256, t256>>>(el, er, src, dst, m, ex);
    k_fix_m<<<(NHtot + 255) / 256, t256>>>(m, NHtot);
    k_edge_exp<<<(EH + 255) / 256, t256>>>(dst, m, ex, s);
    k_zero<<<(NN * 512 + 255) / 256, t256>>>(out, NN * 512);
    k_aggregate<<<aggBlocks, 256>>>(proj2, ex, s, src, dst, out, 128);
    k_finalize<<<(NN * 512 + 255) / 256, t256>>>(out, b2, NN * 512, 512, 0);
}

// round 7
// speedup vs baseline: 3.8699x; 1.9201x over previous
#include <cuda_runtime.h>
#include <math.h>

#define NN 50000
#define NE 800000
#define NH 4
#define NEG 0.2f

// ---------------- scratch (static device globals; no allocs allowed) ----------
__device__ float g_proj1[NN * 400];
__device__ float g_x1[NN * 400];
__device__ float g_proj2[NN * 512];
__device__ float g_el[NN * NH];
__device__ float g_er[NN * NH];
__device__ int   g_rowptr[NN + 1];
__device__ int   g_cnt[NN];
__device__ int   g_bsum[64];
__device__ int   g_ssrc[NE];          // src ids sorted by dst (CSR payload)

// ---------------- helpers ----------------------------------------------------
__device__ __forceinline__ float lrelu(float v) { return v > 0.f ? v : NEG * v; }

__device__ __forceinline__ unsigned f2tf32(float f) {
    unsigned r;
    asm("cvt.rna.tf32.f32 %0, %1;" : "=r"(r) : "f"(f));
    return r;
}

__device__ __forceinline__ void mma_tf32(float c[4], const unsigned a[4], const unsigned b[2]) {
    asm volatile(
        "mma.sync.aligned.m16n8k8.row.col.f32.tf32.tf32.f32 "
        "{%0,%1,%2,%3}, {%4,%5,%6,%7}, {%8,%9}, {%0,%1,%2,%3};"
        : "+f"(c[0]), "+f"(c[1]), "+f"(c[2]), "+f"(c[3])
        : "r"(a[0]), "r"(a[1]), "r"(a[2]), "r"(a[3]), "r"(b[0]), "r"(b[1]));
}

// ---------------- CSR build ---------------------------------------------------
__global__ void k_zero_int(int* p, int n) {
    int i = blockIdx.x * blockDim.x + threadIdx.x;
    if (i < n) p[i] = 0;
}

__global__ void k_hist(const int* __restrict__ dst, int* __restrict__ cnt) {
    int i = blockIdx.x * blockDim.x + threadIdx.x;
    if (i < NE) atomicAdd(&cnt[dst[i]], 1);
}

// block b: inclusive scan of cnt[b*1024 .. ) into rowptr[i+1]; blocksum out
__global__ void k_scan1(const int* __restrict__ cnt, int* __restrict__ rowptr,
                        int* __restrict__ bsum) {
    __shared__ int sd[1024];
    int i = blockIdx.x * 1024 + threadIdx.x;
    int v = (i < NN) ? cnt[i] : 0;
    sd[threadIdx.x] = v;
    __syncthreads();
#pragma unroll
    for (int o = 1; o < 1024; o <<= 1) {
        int t = (threadIdx.x >= o) ? sd[threadIdx.x - o] : 0;
        __syncthreads();
        sd[threadIdx.x] += t;
        __syncthreads();
    }
    if (i < NN) rowptr[i + 1] = sd[threadIdx.x];
    if (threadIdx.x == 1023) bsum[blockIdx.x] = sd[1023];
}

__global__ void k_scan2(int* bsum, int nb) {
    if (threadIdx.x == 0) {
        int acc = 0;
        for (int b = 0; b < nb; b++) { int t = bsum[b]; bsum[b] = acc; acc += t; }
    }
}

__global__ void k_scan3(int* __restrict__ rowptr, const int* __restrict__ bsum,
                        int* __restrict__ cnt) {
    int i = blockIdx.x * blockDim.x + threadIdx.x;
    if (i < NN) {
        rowptr[i + 1] += bsum[i >> 10];
        cnt[i] = 0;
        if (i == 0) rowptr[0] = 0;
    }
}

__global__ void k_scatter(const int* __restrict__ src, const int* __restrict__ dst,
                          const int* __restrict__ rowptr, int* __restrict__ cnt,
                          int* __restrict__ ssrc) {
    int i = blockIdx.x * blockDim.x + threadIdx.x;
    if (i >= NE) return;
    int d = dst[i];
    int pos = rowptr[d] + atomicAdd(&cnt[d], 1);
    ssrc[pos] = src[i];
}

// ---------------- TF32 tensor-core GEMM: C[MxN] = A[MxK]*B[KxN] row-major ----
#define BM 128
#define BN 128
#define BK 16
#define A_STRIDE (BK + 4)
#define B_STRIDE (BN + 8)

__global__ void __launch_bounds__(256, 2)
k_gemm_tf32(const float* __restrict__ A, const float* __restrict__ B,
            float* __restrict__ C, int M, int N, int K) {
    __shared__ unsigned As[BM][A_STRIDE];
    __shared__ unsigned Bs[BK][B_STRIDE];

    const int tid  = threadIdx.x;
    const int lane = tid & 31;
    const int warp = tid >> 5;
    const int g    = lane >> 2;
    const int t4   = lane & 3;
    const int wm   = warp & 1;
    const int wn   = warp >> 1;
    const int bm0  = blockIdx.y * BM;
    const int bn0  = blockIdx.x * BN;

    float c[4][4][4];
#pragma unroll
    for (int mi = 0; mi < 4; mi++)
#pragma unroll
        for (int ni = 0; ni < 4; ni++)
#pragma unroll
            for (int q = 0; q < 4; q++) c[mi][ni][q] = 0.f;

    const int nk = (K + BK - 1) / BK;
    for (int kt = 0; kt < nk; kt++) {
        const int k0 = kt * BK;
#pragma unroll
        for (int u = 0; u < 2; u++) {
            int idx = tid + u * 256;
            int row = idx >> 2;
            int col = (idx & 3) * 4;
            int gm = bm0 + row, gk = k0 + col;
            float4 v = make_float4(0.f, 0.f, 0.f, 0.f);
            if (gm < M) {
                if (gk + 3 < K) v = *(const float4*)(A + (size_t)gm * K + gk);
                else {
                    const float* ap = A + (size_t)gm * K;
                    if (gk + 0 < K) v.x = ap[gk + 0];
                    if (gk + 1 < K) v.y = ap[gk + 1];
                    if (gk + 2 < K) v.z = ap[gk + 2];
                }
            }
            As[row][col + 0] = f2tf32(v.x);
            As[row][col + 1] = f2tf32(v.y);
            As[row][col + 2] = f2tf32(v.z);
            As[row][col + 3] = f2tf32(v.w);
        }
#pragma unroll
        for (int u = 0; u < 2; u++) {
            int idx = tid + u * 256;
            int row = idx >> 5;
            int col = (idx & 31) * 4;
            int gk = k0 + row, gn = bn0 + col;
            float4 v = make_float4(0.f, 0.f, 0.f, 0.f);
            if (gk < K) {
                if (gn + 3 < N) v = *(const float4*)(B + (size_t)gk * N + gn);
                else {
                    const float* bp = B + (size_t)gk * N;
                    if (gn + 0 < N) v.x = bp[gn + 0];
                    if (gn + 1 < N) v.y = bp[gn + 1];
                    if (gn + 2 < N) v.z = bp[gn + 2];
                }
            }
            Bs[row][col + 0] = f2tf32(v.x);
            Bs[row][col + 1] = f2tf32(v.y);
            Bs[row][col + 2] = f2tf32(v.z);
            Bs[row][col + 3] = f2tf32(v.w);
        }
        __syncthreads();

#pragma unroll
        for (int kk = 0; kk < BK; kk += 8) {
            unsigned af[4][4], bf[4][2];
#pragma unroll
            for (int mi = 0; mi < 4; mi++) {
                int r0 = wm * 64 + mi * 16;
                af[mi][0] = As[r0 + g    ][kk + t4    ];
                af[mi][1] = As[r0 + g + 8][kk + t4    ];
                af[mi][2] = As[r0 + g    ][kk + t4 + 4];
                af[mi][3] = As[r0 + g + 8][kk + t4 + 4];
            }
#pragma unroll
            for (int ni = 0; ni < 4; ni++) {
                int c0 = wn * 32 + ni * 8;
                bf[ni][0] = Bs[kk + t4    ][c0 + g];
                bf[ni][1] = Bs[kk + t4 + 4][c0 + g];
            }
#pragma unroll
            for (int mi = 0; mi < 4; mi++)
#pragma unroll
                for (int ni = 0; ni < 4; ni++)
                    mma_tf32(c[mi][ni], af[mi], bf[ni]);
        }
        __syncthreads();
    }

#pragma unroll
    for (int mi = 0; mi < 4; mi++) {
        int row0 = bm0 + wm * 64 + mi * 16;
#pragma unroll
        for (int ni = 0; ni < 4; ni++) {
            int col0 = bn0 + wn * 32 + ni * 8 + 2 * t4;
            int r = row0 + g;
            if (r < M) {
                if (col0     < N) C[(size_t)r * N + col0    ] = c[mi][ni][0];
                if (col0 + 1 < N) C[(size_t)r * N + col0 + 1] = c[mi][ni][1];
            }
            r = row0 + g + 8;
            if (r < M) {
                if (col0     < N) C[(size_t)r * N + col0    ] = c[mi][ni][2];
                if (col0 + 1 < N) C[(size_t)r * N + col0 + 1] = c[mi][ni][3];
            }
        }
    }
}

// ---------------- per-node attention scores el/er ----------------------------
__global__ void k_scores(const float* __restrict__ proj,
                         const float* __restrict__ al, const float* __restrict__ ar,
                         float* __restrict__ el, float* __restrict__ er, int Dh) {
    int n = blockIdx.x;
    int w = threadIdx.x >> 5, lane = threadIdx.x & 31;
    const float* p = proj + (size_t)n * NH * Dh + w * Dh;
    float sl = 0.f, sr = 0.f;
    for (int d = lane; d < Dh; d += 32) {
        float v = p[d];
        sl += v * al[w * Dh + d];
        sr += v * ar[w * Dh + d];
    }
#pragma unroll
    for (int o = 16; o > 0; o >>= 1) {
        sl += __shfl_down_sync(0xffffffffu, sl, o);
        sr += __shfl_down_sync(0xffffffffu, sr, o);
    }
    if (lane == 0) { el[n * NH + w] = sl; er[n * NH + w] = sr; }
}

// ---------------- fused per-dst-node softmax + aggregate + bias + act --------
// 128 threads/block, one block per dst node. DH in {100, 128}; F = 4*DH.
template <int DH>
__global__ void __launch_bounds__(128)
k_node(const float* __restrict__ proj, const float* __restrict__ el,
       const float* __restrict__ er, const int* __restrict__ rowptr,
       const int* __restrict__ ssrc, const float* __restrict__ bias,
       float* __restrict__ out, int act) {
    const int F = NH * DH;
    int n = blockIdx.x;
    int tid = threadIdx.x, w = tid >> 5, lane = tid & 31;
    int beg = rowptr[n], deg = rowptr[n + 1] - beg;
    float* o = out + (size_t)n * F;

    if (deg == 0) {   // uniform across block: safe early return
        for (int f = tid; f < F; f += 128) {
            float v = bias[f];
            o[f] = act ? lrelu(v) : v;
        }
        return;
    }

    __shared__ float s_er[NH], s_m[NH], s_is[NH];
    __shared__ float s_alpha[32 * NH];
    __shared__ int   s_src[32];
    if (tid < NH) s_er[tid] = er[n * NH + tid];
    __syncthreads();

    // ---- phase A: warp w owns head w; max then sum-of-exp (no atomics) ----
    float erw = s_er[w];
    float mx = -INFINITY;
    for (int e = lane; e < deg; e += 32) {
        int s = ssrc[beg + e];
        mx = fmaxf(mx, lrelu(el[s * NH + w] + erw));
    }
#pragma unroll
    for (int off = 16; off; off >>= 1) mx = fmaxf(mx, __shfl_xor_sync(0xffffffffu, mx, off));
    float sum = 0.f;
    for (int e = lane; e < deg; e += 32) {
        int s = ssrc[beg + e];
        sum += expf(lrelu(el[s * NH + w] + erw) - mx);
    }
#pragma unroll
    for (int off = 16; off; off >>= 1) sum += __shfl_xor_sync(0xffffffffu, sum, off);
    if (lane == 0) { s_m[w] = mx; s_is[w] = 1.f / (sum + 1e-9f); }

    // ---- phase B: register accumulate, float4 gather, chunks of 32 edges ----
    const int f = tid * 4;                 // each thread owns 4 consecutive feats
    const int h = f / DH;                  // DH%4==0 -> same head for all 4
    float4 acc = make_float4(0.f, 0.f, 0.f, 0.f);

    for (int c0 = 0; c0 < deg; c0 += 32) {
        int cn = min(32, deg - c0);
        __syncthreads();
        for (int i = tid; i < cn * NH; i += 128) {
            int e = i >> 2, hh = i & 3;
            int s = ssrc[beg + c0 + e];
            if (hh == 0) s_src[e] = s;
            s_alpha[i] = expf(lrelu(el[s * NH + hh] + s_er[hh]) - s_m[hh]) * s_is[hh];
        }
        __syncthreads();
        if (f < F) {
            for (int e = 0; e < cn; e++) {
                float a = s_alpha[e * NH + h];
                float4 v = *(const float4*)(proj + (size_t)s_src[e] * F + f);
                acc.x += v.x * a;
                acc.y += v.y * a;
                acc.z += v.z * a;
                acc.w += v.w * a;
            }
        }
    }

    if (f < F) {
        float4 b4 = *(const float4*)(bias + f);
        float4 r;
        r.x = acc.x + b4.x; r.y = acc.y + b4.y;
        r.z = acc.z + b4.z; r.w = acc.w + b4.w;
        if (act) { r.x = lrelu(r.x); r.y = lrelu(r.y); r.z = lrelu(r.z); r.w = lrelu(r.w); }
        *(float4*)(o + f) = r;
    }
}

// ---------------- launch -----------------------------------------------------
extern "C" void kernel_launch(void* const* d_in, const int* in_sizes, int n_in,
                              void* d_out, int out_size) {
    const float* init_emb = (const float*)d_in[0];
    const float* W1  = (const float*)d_in[1];
    const float* al1 = (const float*)d_in[2];
    const float* ar1 = (const float*)d_in[3];
    const float* b1  = (const float*)d_in[4];
    const float* W2  = (const float*)d_in[5];
    const float* al2 = (const float*)d_in[6];
    const float* ar2 = (const float*)d_in[7];
    const float* b2  = (const float*)d_in[8];
    const int*   src = (const int*)d_in[9];
    const int*   dst = (const int*)d_in[10];
    float* out = (float*)d_out;

    float *proj1, *x1, *proj2, *el, *er;
    int *rowptr, *cnt, *bsum, *ssrc;
    cudaGetSymbolAddress((void**)&proj1,  g_proj1);
    cudaGetSymbolAddress((void**)&x1,     g_x1);
    cudaGetSymbolAddress((void**)&proj2,  g_proj2);
    cudaGetSymbolAddress((void**)&el,     g_el);
    cudaGetSymbolAddress((void**)&er,     g_er);
    cudaGetSymbolAddress((void**)&rowptr, g_rowptr);
    cudaGetSymbolAddress((void**)&cnt,    g_cnt);
    cudaGetSymbolAddress((void**)&bsum,   g_bsum);
    cudaGetSymbolAddress((void**)&ssrc,   g_ssrc);

    dim3 t256(256);
    const int nScanBlocks = (NN + 1023) / 1024;   // 49

    // ---------------- CSR build (by dst) -------------------------------------
    k_zero_int<<<(NN + 255) / 256, t256>>>(cnt, NN);
    k_hist<<<(NE + 255) / 256, t256>>>(dst, cnt);
    k_scan1<<<nScanBlocks, 1024>>>(cnt, rowptr, bsum);
    k_scan2<<<1, 32>>>(bsum, nScanBlocks);
    k_scan3<<<nScanBlocks, 1024>>>(rowptr, bsum, cnt);
    k_scatter<<<(NE + 255) / 256, t256>>>(src, dst, rowptr, cnt, ssrc);

    // ===================== layer 1 (Fin=300, Fout=400, Dh=100) ===============
    {
        dim3 grid((400 + BN - 1) / BN, (NN + BM - 1) / BM);
        k_gemm_tf32<<<grid, 256>>>(init_emb, W1, proj1, NN, 400, 300);
    }
    k_scores<<<NN, 128>>>(proj1, al1, ar1, el, er, 100);
    k_node<100><<<NN, 128>>>(proj1, el, er, rowptr, ssrc, b1, x1, 1);

    // ===================== layer 2 (Fin=400, Fout=512, Dh=128) ===============
    {
        dim3 grid((512 + BN - 1) / BN, (NN + BM - 1) / BM);
        k_gemm_tf32<<<grid, 256>>>(x1, W2, proj2, NN, 512, 400);
    }
    k_scores<<<NN, 128>>>(proj2, al2, ar2, el, er, 128);
    k_node<128><<<NN, 128>>>(proj2, el, er, rowptr, ssrc, b2, out, 0);
}

// round 10
// speedup vs baseline: 5.4154x; 1.3993x over previous
#include <cuda_runtime.h>
#include <math.h>

#define NN 50000
#define NE 800000
#define NH 4
#define NEG 0.2f

// ---------------- scratch (static device globals; no allocs allowed) ----------
__device__ float g_proj1[NN * 400];
__device__ float g_x1[NN * 400];
__device__ float g_proj2[NN * 512];
__device__ float g_el[NN * NH];
__device__ float g_er[NN * NH];
__device__ int   g_rowptr[NN + 1];
__device__ int   g_cnt[NN];
__device__ int   g_bsum[64];
__device__ int   g_ssrc[NE];

// ---------------- helpers ----------------------------------------------------
__device__ __forceinline__ float lrelu(float v) { return v > 0.f ? v : NEG * v; }

__device__ __forceinline__ unsigned f2tf32(float f) {
    unsigned r;
    asm("cvt.rna.tf32.f32 %0, %1;" : "=r"(r) : "f"(f));
    return r;
}

__device__ __forceinline__ void mma_tf32(float c[4], const unsigned a[4], const unsigned b[2]) {
    asm volatile(
        "mma.sync.aligned.m16n8k8.row.col.f32.tf32.tf32.f32 "
        "{%0,%1,%2,%3}, {%4,%5,%6,%7}, {%8,%9}, {%0,%1,%2,%3};"
        : "+f"(c[0]), "+f"(c[1]), "+f"(c[2]), "+f"(c[3])
        : "r"(a[0]), "r"(a[1]), "r"(a[2]), "r"(a[3]), "r"(b[0]), "r"(b[1]));
}

// ---------------- CSR build ---------------------------------------------------
__global__ void k_zero_int(int* p, int n) {
    int i = blockIdx.x * blockDim.x + threadIdx.x;
    if (i < n) p[i] = 0;
}

__global__ void k_hist(const int* __restrict__ dst, int* __restrict__ cnt) {
    int i = blockIdx.x * blockDim.x + threadIdx.x;
    if (i < NE) atomicAdd(&cnt[dst[i]], 1);
}

__global__ void k_scan1(const int* __restrict__ cnt, int* __restrict__ rowptr,
                        int* __restrict__ bsum) {
    __shared__ int sd[1024];
    int i = blockIdx.x * 1024 + threadIdx.x;
    int v = (i < NN) ? cnt[i] : 0;
    sd[threadIdx.x] = v;
    __syncthreads();
#pragma unroll
    for (int o = 1; o < 1024; o <<= 1) {
        int t = (threadIdx.x >= o) ? sd[threadIdx.x - o] : 0;
        __syncthreads();
        sd[threadIdx.x] += t;
        __syncthreads();
    }
    if (i < NN) rowptr[i + 1] = sd[threadIdx.x];
    if (threadIdx.x == 1023) bsum[blockIdx.x] = sd[1023];
}

__global__ void k_scan2(int* bsum, int nb) {
    if (threadIdx.x == 0) {
        int acc = 0;
        for (int b = 0; b < nb; b++) { int t = bsum[b]; bsum[b] = acc; acc += t; }
    }
}

__global__ void k_scan3(int* __restrict__ rowptr, const int* __restrict__ bsum,
                        int* __restrict__ cnt) {
    int i = blockIdx.x * blockDim.x + threadIdx.x;
    if (i < NN) {
        rowptr[i + 1] += bsum[i >> 10];
        cnt[i] = 0;
        if (i == 0) rowptr[0] = 0;
    }
}

__global__ void k_scatter(const int* __restrict__ src, const int* __restrict__ dst,
                          const int* __restrict__ rowptr, int* __restrict__ cnt,
                          int* __restrict__ ssrc) {
    int i = blockIdx.x * blockDim.x + threadIdx.x;
    if (i >= NE) return;
    int d = dst[i];
    int pos = rowptr[d] + atomicAdd(&cnt[d], 1);
    ssrc[pos] = src[i];
}

// ---------------- TF32 GEMM, register-staged double buffering ----------------
#define BM 128
#define BN 128
#define BK 16
#define A_STRIDE (BK + 4)
#define B_STRIDE (BN + 8)

__device__ __forceinline__ void load_tileA(const float* __restrict__ A, int M, int K,
                                           int bm0, int k0, int tid, float4 pa[2]) {
#pragma unroll
    for (int u = 0; u < 2; u++) {
        int idx = tid + u * 256;
        int row = idx >> 2;
        int col = (idx & 3) * 4;
        int gm = bm0 + row, gk = k0 + col;
        float4 v = make_float4(0.f, 0.f, 0.f, 0.f);
        if (gm < M) {
            if (gk + 3 < K) v = *(const float4*)(A + (size_t)gm * K + gk);
            else {
                const float* ap = A + (size_t)gm * K;
                if (gk + 0 < K) v.x = ap[gk + 0];
                if (gk + 1 < K) v.y = ap[gk + 1];
                if (gk + 2 < K) v.z = ap[gk + 2];
            }
        }
        pa[u] = v;
    }
}

__device__ __forceinline__ void load_tileB(const float* __restrict__ B, int N, int K,
                                           int bn0, int k0, int tid, float4 pb[2]) {
#pragma unroll
    for (int u = 0; u < 2; u++) {
        int idx = tid + u * 256;
        int row = idx >> 5;
        int col = (idx & 31) * 4;
        int gk = k0 + row, gn = bn0 + col;
        float4 v = make_float4(0.f, 0.f, 0.f, 0.f);
        if (gk < K) {
            if (gn + 3 < N) v = *(const float4*)(B + (size_t)gk * N + gn);
            else {
                const float* bp = B + (size_t)gk * N;
                if (gn + 0 < N) v.x = bp[gn + 0];
                if (gn + 1 < N) v.y = bp[gn + 1];
                if (gn + 2 < N) v.z = bp[gn + 2];
            }
        }
        pb[u] = v;
    }
}

__device__ __forceinline__ void store_tileA(unsigned (*As)[A_STRIDE], int tid,
                                            const float4 pa[2]) {
#pragma unroll
    for (int u = 0; u < 2; u++) {
        int idx = tid + u * 256;
        int row = idx >> 2;
        int col = (idx & 3) * 4;
        As[row][col + 0] = f2tf32(pa[u].x);
        As[row][col + 1] = f2tf32(pa[u].y);
        As[row][col + 2] = f2tf32(pa[u].z);
        As[row][col + 3] = f2tf32(pa[u].w);
    }
}

__device__ __forceinline__ void store_tileB(unsigned (*Bs)[B_STRIDE], int tid,
                                            const float4 pb[2]) {
#pragma unroll
    for (int u = 0; u < 2; u++) {
        int idx = tid + u * 256;
        int row = idx >> 5;
        int col = (idx & 31) * 4;
        Bs[row][col + 0] = f2tf32(pb[u].x);
        Bs[row][col + 1] = f2tf32(pb[u].y);
        Bs[row][col + 2] = f2tf32(pb[u].z);
        Bs[row][col + 3] = f2tf32(pb[u].w);
    }
}

__global__ void __launch_bounds__(256, 2)
k_gemm_tf32(const float* __restrict__ A, const float* __restrict__ B,
            float* __restrict__ C, int M, int N, int K) {
    __shared__ unsigned As[2][BM][A_STRIDE];
    __shared__ unsigned Bs[2][BK][B_STRIDE];

    const int tid  = threadIdx.x;
    const int lane = tid & 31;
    const int warp = tid >> 5;
    const int g    = lane >> 2;
    const int t4   = lane & 3;
    const int wm   = warp & 1;
    const int wn   = warp >> 1;
    const int bm0  = blockIdx.y * BM;
    const int bn0  = blockIdx.x * BN;

    float c[4][4][4];
#pragma unroll
    for (int mi = 0; mi < 4; mi++)
#pragma unroll
        for (int ni = 0; ni < 4; ni++)
#pragma unroll
            for (int q = 0; q < 4; q++) c[mi][ni][q] = 0.f;

    const int nk = (K + BK - 1) / BK;
    float4 pa[2], pb[2];

    load_tileA(A, M, K, bm0, 0, tid, pa);
    load_tileB(B, N, K, bn0, 0, tid, pb);
    store_tileA(As[0], tid, pa);
    store_tileB(Bs[0], tid, pb);
    __syncthreads();

    int buf = 0;
    for (int kt = 0; kt < nk; kt++) {
        // prefetch next tile into registers (LDGs overlap the MMAs below)
        if (kt + 1 < nk) {
            load_tileA(A, M, K, bm0, (kt + 1) * BK, tid, pa);
            load_tileB(B, N, K, bn0, (kt + 1) * BK, tid, pb);
        }

#pragma unroll
        for (int kk = 0; kk < BK; kk += 8) {
            unsigned af[4][4], bf[4][2];
#pragma unroll
            for (int mi = 0; mi < 4; mi++) {
                int r0 = wm * 64 + mi * 16;
                af[mi][0] = As[buf][r0 + g    ][kk + t4    ];
                af[mi][1] = As[buf][r0 + g + 8][kk + t4    ];
                af[mi][2] = As[buf][r0 + g    ][kk + t4 + 4];
                af[mi][3] = As[buf][r0 + g + 8][kk + t4 + 4];
            }
#pragma unroll
            for (int ni = 0; ni < 4; ni++) {
                int c0 = wn * 32 + ni * 8;
                bf[ni][0] = Bs[buf][kk + t4    ][c0 + g];
                bf[ni][1] = Bs[buf][kk + t4 + 4][c0 + g];
            }
#pragma unroll
            for (int mi = 0; mi < 4; mi++)
#pragma unroll
                for (int ni = 0; ni < 4; ni++)
                    mma_tf32(c[mi][ni], af[mi], bf[ni]);
        }

        if (kt + 1 < nk) {
            store_tileA(As[buf ^ 1], tid, pa);
            store_tileB(Bs[buf ^ 1], tid, pb);
        }
        __syncthreads();
        buf ^= 1;
    }

#pragma unroll
    for (int mi = 0; mi < 4; mi++) {
        int row0 = bm0 + wm * 64 + mi * 16;
#pragma unroll
        for (int ni = 0; ni < 4; ni++) {
            int col0 = bn0 + wn * 32 + ni * 8 + 2 * t4;
            int r = row0 + g;
            if (r < M) {
                if (col0     < N) C[(size_t)r * N + col0    ] = c[mi][ni][0];
                if (col0 + 1 < N) C[(size_t)r * N + col0 + 1] = c[mi][ni][1];
            }
            r = row0 + g + 8;
            if (r < M) {
                if (col0     < N) C[(size_t)r * N + col0    ] = c[mi][ni][2];
                if (col0 + 1 < N) C[(size_t)r * N + col0 + 1] = c[mi][ni][3];
            }
        }
    }
}

// ---------------- per-node attention scores el/er ----------------------------
__global__ void k_scores(const float* __restrict__ proj,
                         const float* __restrict__ al, const float* __restrict__ ar,
                         float* __restrict__ el, float* __restrict__ er, int Dh) {
    int n = blockIdx.x;
    int w = threadIdx.x >> 5, lane = threadIdx.x & 31;
    const float* p = proj + (size_t)n * NH * Dh + w * Dh;
    float sl = 0.f, sr = 0.f;
    for (int d = lane; d < Dh; d += 32) {
        float v = p[d];
        sl += v * al[w * Dh + d];
        sr += v * ar[w * Dh + d];
    }
#pragma unroll
    for (int o = 16; o > 0; o >>= 1) {
        sl += __shfl_down_sync(0xffffffffu, sl, o);
        sr += __shfl_down_sync(0xffffffffu, sr, o);
    }
    if (lane == 0) { el[n * NH + w] = sl; er[n * NH + w] = sr; }
}

// ---------------- fused per-dst-node softmax + aggregate + bias + act --------
template <int DH>
__global__ void __launch_bounds__(128)
k_node(const float* __restrict__ proj, const float* __restrict__ el,
       const float* __restrict__ er, const int* __restrict__ rowptr,
       const int* __restrict__ ssrc, const float* __restrict__ bias,
       float* __restrict__ out, int act) {
    const int F = NH * DH;
    int n = blockIdx.x;
    int tid = threadIdx.x, w = tid >> 5, lane = tid & 31;
    int beg = rowptr[n], deg = rowptr[n + 1] - beg;
    float* o = out + (size_t)n * F;

    if (deg == 0) {
        for (int f = tid; f < F; f += 128) {
            float v = bias[f];
            o[f] = act ? lrelu(v) : v;
        }
        return;
    }

    __shared__ float s_er[NH], s_m[NH], s_is[NH];
    __shared__ float s_alpha[32 * NH];
    __shared__ int   s_src[32];
    if (tid < NH) s_er[tid] = er[n * NH + tid];
    __syncthreads();

    float erw = s_er[w];
    float mx = -INFINITY;
    for (int e = lane; e < deg; e += 32) {
        int s = ssrc[beg + e];
        mx = fmaxf(mx, lrelu(el[s * NH + w] + erw));
    }
#pragma unroll
    for (int off = 16; off; off >>= 1) mx = fmaxf(mx, __shfl_xor_sync(0xffffffffu, mx, off));
    float sum = 0.f;
    for (int e = lane; e < deg; e += 32) {
        int s = ssrc[beg + e];
        sum += expf(lrelu(el[s * NH + w] + erw) - mx);
    }
#pragma unroll
    for (int off = 16; off; off >>= 1) sum += __shfl_xor_sync(0xffffffffu, sum, off);
    if (lane == 0) { s_m[w] = mx; s_is[w] = 1.f / (sum + 1e-9f); }

    const int f = tid * 4;
    const int h = f / DH;
    float4 acc = make_float4(0.f, 0.f, 0.f, 0.f);

    for (int c0 = 0; c0 < deg; c0 += 32) {
        int cn = min(32, deg - c0);
        __syncthreads();
        for (int i = tid; i < cn * NH; i += 128) {
            int e = i >> 2, hh = i & 3;
            int s = ssrc[beg + c0 + e];
            if (hh == 0) s_src[e] = s;
            s_alpha[i] = expf(lrelu(el[s * NH + hh] + s_er[hh]) - s_m[hh]) * s_is[hh];
        }
        __syncthreads();
        if (f < F) {
            for (int e = 0; e < cn; e++) {
                float a = s_alpha[e * NH + h];
                float4 v = *(const float4*)(proj + (size_t)s_src[e] * F + f);
                acc.x += v.x * a;
                acc.y += v.y * a;
                acc.z += v.z * a;
                acc.w += v.w * a;
            }
        }
    }

    if (f < F) {
        float4 b4 = *(const float4*)(bias + f);
        float4 r;
        r.x = acc.x + b4.x; r.y = acc.y + b4.y;
        r.z = acc.z + b4.z; r.w = acc.w + b4.w;
        if (act) { r.x = lrelu(r.x); r.y = lrelu(r.y); r.z = lrelu(r.z); r.w = lrelu(r.w); }
        *(float4*)(o + f) = r;
    }
}

// ---------------- launch -----------------------------------------------------
extern "C" void kernel_launch(void* const* d_in, const int* in_sizes, int n_in,
                              void* d_out, int out_size) {
    const float* init_emb = (const float*)d_in[0];
    const float* W1  = (const float*)d_in[1];
    const float* al1 = (const float*)d_in[2];
    const float* ar1 = (const float*)d_in[3];
    const float* b1  = (const float*)d_in[4];
    const float* W2  = (const float*)d_in[5];
    const float* al2 = (const float*)d_in[6];
    const float* ar2 = (const float*)d_in[7];
    const float* b2  = (const float*)d_in[8];
    const int*   src = (const int*)d_in[9];
    const int*   dst = (const int*)d_in[10];
    float* out = (float*)d_out;

    float *proj1, *x1, *proj2, *el, *er;
    int *rowptr, *cnt, *bsum, *ssrc;
    cudaGetSymbolAddress((void**)&proj1,  g_proj1);
    cudaGetSymbolAddress((void**)&x1,     g_x1);
    cudaGetSymbolAddress((void**)&proj2,  g_proj2);
    cudaGetSymbolAddress((void**)&el,     g_el);
    cudaGetSymbolAddress((void**)&er,     g_er);
    cudaGetSymbolAddress((void**)&rowptr, g_rowptr);
    cudaGetSymbolAddress((void**)&cnt,    g_cnt);
    cudaGetSymbolAddress((void**)&bsum,   g_bsum);
    cudaGetSymbolAddress((void**)&ssrc,   g_ssrc);

    dim3 t256(256);
    const int nScanBlocks = (NN + 1023) / 1024;

    // lazily-created side stream + events for capture-legal fork/join
    static cudaStream_t s_side = nullptr;
    static cudaEvent_t  s_evFork = nullptr, s_evJoin = nullptr;
    if (!s_side) {
        if (cudaStreamCreateWithFlags(&s_side, cudaStreamNonBlocking) != cudaSuccess)
            s_side = nullptr;
        if (s_side) {
            cudaEventCreateWithFlags(&s_evFork, cudaEventDisableTiming);
            cudaEventCreateWithFlags(&s_evJoin, cudaEventDisableTiming);
        }
    }

    // capture stream is the legacy default stream (stream 0)
    cudaStream_t main_s = 0;
    cudaStream_t csr_s  = s_side ? s_side : main_s;

    if (s_side) {
        cudaEventRecord(s_evFork, main_s);
        cudaStreamWaitEvent(csr_s, s_evFork, 0);
    }

    // ---------------- CSR build (side stream, overlaps GEMM1) ----------------
    k_zero_int<<<(NN + 255) / 256, t256, 0, csr_s>>>(cnt, NN);
    k_hist<<<(NE + 255) / 256, t256, 0, csr_s>>>(dst, cnt);
    k_scan1<<<nScanBlocks, 1024, 0, csr_s>>>(cnt, rowptr, bsum);
    k_scan2<<<1, 32, 0, csr_s>>>(bsum, nScanBlocks);
    k_scan3<<<nScanBlocks, 1024, 0, csr_s>>>(rowptr, bsum, cnt);
    k_scatter<<<(NE + 255) / 256, t256, 0, csr_s>>>(src, dst, rowptr, cnt, ssrc);

    if (s_side) cudaEventRecord(s_evJoin, csr_s);

    // ===================== layer 1 (Fin=300, Fout=400, Dh=100) ===============
    {
        dim3 grid((400 + BN - 1) / BN, (NN + BM - 1) / BM);
        k_gemm_tf32<<<grid, 256, 0, main_s>>>(init_emb, W1, proj1, NN, 400, 300);
    }
    k_scores<<<NN, 128, 0, main_s>>>(proj1, al1, ar1, el, er, 100);

    if (s_side) cudaStreamWaitEvent(main_s, s_evJoin, 0);   // join before k_node

    k_node<100><<<NN, 128, 0, main_s>>>(proj1, el, er, rowptr, ssrc, b1, x1, 1);

    // ===================== layer 2 (Fin=400, Fout=512, Dh=128) ===============
    {
        dim3 grid((512 + BN - 1) / BN, (NN + BM - 1) / BM);
        k_gemm_tf32<<<grid, 256, 0, main_s>>>(x1, W2, proj2, NN, 512, 400);
    }
    k_scores<<<NN, 128, 0, main_s>>>(proj2, al2, ar2, el, er, 128);
    k_node<128><<<NN, 128, 0, main_s>>>(proj2, el, er, rowptr, ssrc, b2, out, 0);
}